// round 9
// baseline (speedup 1.0000x reference)
#include <cuda_runtime.h>
#include <cuda_bf16.h>
#include <stdint.h>

#define NN   50000
#define NE   800000
#define FIN  128
#define DIM  256
#define NG   512
#define NL   3
#define OUTD (NL*DIM)   // 768
#define BN_EPS 1e-5f

// Scratch
__device__ float4 g_bufA4[NN*DIM/4];   // h (layer output)
__device__ float4 g_bufB4[NN*DIM/4];   // agg, then m (post-MLP)
__device__ float4 g_bufC4[NN*DIM/4];   // t (hidden)
__device__ float  g_stats[2*DIM];      // per-column sum, sumsq
__device__ int    g_idx64;             // 1 if edge_index/batch are int64
// Pre-split bf16 weight images, N-major ([n][k]) per (bn,chunk) 128x32 tile.
__device__ __nv_bfloat16 g_whi[360448];
__device__ __nv_bfloat16 g_wlo[360448];
// CSR scratch
__device__ int g_deg[NN];
__device__ int g_rowstart[NN];
__device__ int g_pos[NE];
__device__ int g_src32[NE];
__device__ int g_dst32[NE];
__device__ int g_eidx[NE];

// ---------------------------------------------------------------------------
__device__ __forceinline__ uint32_t smem_u32(const void* p) {
    uint32_t a;
    asm("{ .reg .u64 t; cvta.to.shared.u64 t, %1; cvt.u32.u64 %0, t; }" : "=r"(a) : "l"(p));
    return a;
}
__device__ __forceinline__ uint32_t pack_bf2(float a, float b) {
    uint32_t r;
    asm("cvt.rn.bf16x2.f32 %0, %1, %2;" : "=r"(r) : "f"(b), "f"(a));
    return r;
}
__device__ __forceinline__ void splitbf(float x, float& h, float& l) {
    __nv_bfloat16 hb = __float2bfloat16_rn(x);
    h = __bfloat162float(hb);
    l = x - h;
}
#define LDSM_X4(r0, r1, r2, r3, addr)                                          \
    asm volatile("ldmatrix.sync.aligned.m8n8.x4.shared.b16 {%0,%1,%2,%3}, [%4];" \
                 : "=r"(r0), "=r"(r1), "=r"(r2), "=r"(r3) : "r"(addr))
#define MMA_BF16(c, a0, a1, a2, a3, b0, b1)                                    \
    asm volatile(                                                              \
        "mma.sync.aligned.m16n8k16.row.col.f32.bf16.bf16.f32 "                 \
        "{%0,%1,%2,%3}, {%4,%5,%6,%7}, {%8,%9}, {%0,%1,%2,%3};"                \
        : "+f"(c[0]), "+f"(c[1]), "+f"(c[2]), "+f"(c[3])                       \
        : "r"(a0), "r"(a1), "r"(a2), "r"(a3), "r"(b0), "r"(b1))

__device__ __forceinline__ long long load_idx(const void* p, long long i, int is64) {
    return is64 ? ((const long long*)p)[i] : (long long)((const int*)p)[i];
}

// ---------------------------------------------------------------------------
// zero pooled + degree counters + index dtype detect (thread 0)
__global__ void zeroall_kernel(float* pooled, const unsigned int* ei_raw) {
    int i = blockIdx.x * blockDim.x + threadIdx.x;
    if (i < NG * OUTD) pooled[i] = 0.f;
    if (i < NN) g_deg[i] = 0;
    if (i == 0) {
        unsigned int z = 0u;
#pragma unroll
        for (int k = 0; k < 32; k++) z |= ei_raw[2*k + 1];
        g_idx64 = (z == 0u) ? 1 : 0;
    }
}

__global__ void zero_kernel(float* p, int n) {
    int i = blockIdx.x * blockDim.x + threadIdx.x;
    if (i < n) p[i] = 0.f;
}

// ---------------------------------------------------------------------------
// Edge prep (decode indices, degree histogram + slot positions) fused with
// weight prep (fp32 -> hi/lo bf16 N-major images).
#define WTOT 360448
__global__ void prep_kernel(const void* __restrict__ ei,
                            const float* w0, const float* w1, const float* w2,
                            const float* w3, const float* w4, const float* w5,
                            __nv_bfloat16* __restrict__ whi,
                            __nv_bfloat16* __restrict__ wlo) {
    int stride = gridDim.x * blockDim.x;
    int gidx = blockIdx.x * blockDim.x + threadIdx.x;
    int is64 = g_idx64;
    for (int e = gidx; e < NE; e += stride) {
        int s = (int)load_idx(ei, e, is64);
        int d = (int)load_idx(ei, (long long)NE + e, is64);
        g_src32[e] = s;
        g_dst32[e] = d;
        g_pos[e] = atomicAdd(&g_deg[d], 1);
    }
    const float* ws[6] = {w0, w1, w2, w3, w4, w5};
    const int woffs[6] = {0, 32768, 98304, 163840, 229376, 294912};
    for (int idx = gidx; idx < WTOT; idx += stride) {
        int wsel, local, K;
        if (idx < 32768) { wsel = 0; local = idx; K = FIN; }
        else { wsel = 1 + ((idx - 32768) >> 16); local = (idx - 32768) & 65535; K = DIM; }
        int k = local >> 8, n = local & 255;
        int nch = K >> 5;
        int t = n >> 7, nl = n & 127, c = k >> 5, kk = k & 31;
        int off = woffs[wsel] + (t * nch + c) * 4096 + nl * 32 + kk;
        float x = ws[wsel][local];
        float h, l;
        splitbf(x, h, l);
        whi[off] = __float2bfloat16_rn(h);
        wlo[off] = __float2bfloat16_rn(l);
    }
}

// Single-block scan of degrees -> row starts.
__global__ void scan_kernel() {
    __shared__ int sm[1024];
    int t = threadIdx.x;
    const int CH = (NN + 1023) / 1024;
    int b0 = t * CH, b1 = min(b0 + CH, NN);
    int s = 0;
    for (int i = b0; i < b1; i++) s += g_deg[i];
    sm[t] = s;
    __syncthreads();
    for (int off = 1; off < 1024; off <<= 1) {
        int v = (t >= off) ? sm[t - off] : 0;
        __syncthreads();
        sm[t] += v;
        __syncthreads();
    }
    int run = (t == 0) ? 0 : sm[t - 1];
    for (int i = b0; i < b1; i++) { g_rowstart[i] = run; run += g_deg[i]; }
}

__global__ void fillcsr_kernel() {
    int stride = gridDim.x * blockDim.x;
    for (int e = blockIdx.x * blockDim.x + threadIdx.x; e < NE; e += stride)
        g_eidx[g_rowstart[g_dst32[e]] + g_pos[e]] = g_src32[e];
}

// ---------------------------------------------------------------------------
// CSR gather: agg[i] = h[i] + sum_{j in in(i)} h[j].  One warp per node.
__global__ void gather_kernel(const float* __restrict__ h, float* __restrict__ agg,
                              int F) {
    int gw = (blockIdx.x * blockDim.x + threadIdx.x) >> 5;
    if (gw >= NN) return;
    int lane = threadIdx.x & 31;
    int start = g_rowstart[gw], deg = g_deg[gw];
    int F4 = F >> 2;
    bool wide = (F4 == 64);
    const float4* hv = (const float4*)h;
    const float4* hp = hv + (long long)gw * F4 + lane;
    float4 a0 = hp[0];
    float4 a1 = wide ? hp[32] : make_float4(0.f, 0.f, 0.f, 0.f);
    for (int i0 = 0; i0 < deg; i0 += 32) {
        int mye = (i0 + lane < deg) ? g_eidx[start + i0 + lane] : 0;
        int cnt = min(32, deg - i0);
        for (int j = 0; j < cnt; j++) {
            int s = __shfl_sync(0xffffffffu, mye, j);
            const float4* sp = hv + (long long)s * F4 + lane;
            float4 v = sp[0];
            a0.x += v.x; a0.y += v.y; a0.z += v.z; a0.w += v.w;
            if (wide) {
                float4 u = sp[32];
                a1.x += u.x; a1.y += u.y; a1.z += u.z; a1.w += u.w;
            }
        }
    }
    float4* op = (float4*)agg + (long long)gw * F4 + lane;
    op[0] = a0;
    if (wide) op[32] = a1;
}

// ---------------------------------------------------------------------------
// 3xBF16 tensor-core GEMM: C[M,256] = relu(A[M,K] @ W[K,256] + bias).
// Optionally accumulates per-column sum/sumsq of the output into g_stats.
// MMA schedule: three passes (HH, LH, HL) over 16 independent accumulators,
// so consecutive MMAs never share an accumulator (no RAW dependency stalls).
#define ARS 80
#define STAGE 40960

__global__ __launch_bounds__(256) void bf16x3_gemm(
    const float* __restrict__ A, const __nv_bfloat16* __restrict__ Whi,
    const __nv_bfloat16* __restrict__ Wlo, const float* __restrict__ bias,
    float* __restrict__ C, int M, int K, int do_stats) {
    extern __shared__ __align__(16) char dsm[];
    int tid = threadIdx.x, wid = tid >> 5, lane = tid & 31;
    int bm = blockIdx.x, bn = blockIdx.y;
    int nch = K >> 5;

    uint32_t sb = (smem_u32(dsm) + 127) & ~127u;
    int m_off = (wid & 3) * 32;
    int n_off = (wid >> 2) * 64;

    int aRowL = (lane & 7) + ((lane >> 3) & 1) * 8;
    int aColL = (lane >> 4) * 16;
    int bRowL = ((lane >> 4) * 8) + (lane & 7);
    int bColL = ((lane >> 3) & 1) * 16;

    float acc[2][8][4] = {};

    const float* Abase = A + (long long)bm * 128 * K;
    const __nv_bfloat16* WHbase = Whi + (long long)bn * nch * 4096;
    const __nv_bfloat16* WLbase = Wlo + (long long)bn * nch * 4096;

    float4 pa[4];
    uint4 pbh[2], pbl[2];
#pragma unroll
    for (int i = 0; i < 4; i++) {
        int pos = tid + i * 256;
        int row = pos >> 3, c4 = pos & 7;
        pa[i] = make_float4(0.f, 0.f, 0.f, 0.f);
        if (bm * 128 + row < M)
            pa[i] = *(const float4*)(Abase + (long long)row * K + c4 * 4);
    }
#pragma unroll
    for (int i = 0; i < 2; i++) {
        int p = tid + i * 256;
        pbh[i] = ((const uint4*)WHbase)[p];
        pbl[i] = ((const uint4*)WLbase)[p];
    }

    for (int c = 0; c < nch; c++) {
        uint32_t st = sb + (c & 1) * STAGE;
#pragma unroll
        for (int i = 0; i < 4; i++) {
            int pos = tid + i * 256;
            int row = pos >> 3, c4 = pos & 7;
            float h0, l0, h1, l1, h2, l2, h3, l3;
            splitbf(pa[i].x, h0, l0); splitbf(pa[i].y, h1, l1);
            splitbf(pa[i].z, h2, l2); splitbf(pa[i].w, h3, l3);
            uint32_t H01 = pack_bf2(h0, h1), H23 = pack_bf2(h2, h3);
            uint32_t L01 = pack_bf2(l0, l1), L23 = pack_bf2(l2, l3);
            uint32_t ad = st + row * ARS + c4 * 8;
            asm volatile("st.shared.v2.b32 [%0], {%1,%2};"
                         :: "r"(ad), "r"(H01), "r"(H23) : "memory");
            asm volatile("st.shared.v2.b32 [%0], {%1,%2};"
                         :: "r"(ad + 10240), "r"(L01), "r"(L23) : "memory");
        }
#pragma unroll
        for (int i = 0; i < 2; i++) {
            int p = tid + i * 256;
            int row = p >> 2, seg = p & 3;
            uint32_t ad = st + 20480 + row * ARS + seg * 16;
            asm volatile("st.shared.v4.b32 [%0], {%1,%2,%3,%4};"
                         :: "r"(ad), "r"(pbh[i].x), "r"(pbh[i].y), "r"(pbh[i].z), "r"(pbh[i].w) : "memory");
            asm volatile("st.shared.v4.b32 [%0], {%1,%2,%3,%4};"
                         :: "r"(ad + 10240), "r"(pbl[i].x), "r"(pbl[i].y), "r"(pbl[i].z), "r"(pbl[i].w) : "memory");
        }
        __syncthreads();

        if (c + 1 < nch) {
            int k0 = (c + 1) * 32;
#pragma unroll
            for (int i = 0; i < 4; i++) {
                int pos = tid + i * 256;
                int row = pos >> 3, c4 = pos & 7;
                pa[i] = make_float4(0.f, 0.f, 0.f, 0.f);
                if (bm * 128 + row < M)
                    pa[i] = *(const float4*)(Abase + (long long)row * K + k0 + c4 * 4);
            }
            const uint4* sh = (const uint4*)(WHbase + (long long)(c + 1) * 4096);
            const uint4* sl = (const uint4*)(WLbase + (long long)(c + 1) * 4096);
#pragma unroll
            for (int i = 0; i < 2; i++) {
                int p = tid + i * 256;
                pbh[i] = sh[p];
                pbl[i] = sl[p];
            }
        }

#pragma unroll
        for (int ks = 0; ks < 2; ks++) {
            uint32_t aH[2][4], aL[2][4], bH[8][2], bL[8][2];
#pragma unroll
            for (int mt = 0; mt < 2; mt++) {
                uint32_t ad = st + (m_off + mt * 16 + aRowL) * ARS + ks * 32 + aColL;
                LDSM_X4(aH[mt][0], aH[mt][1], aH[mt][2], aH[mt][3], ad);
                LDSM_X4(aL[mt][0], aL[mt][1], aL[mt][2], aL[mt][3], ad + 10240);
            }
#pragma unroll
            for (int p = 0; p < 4; p++) {
                uint32_t ad = st + 20480 + (n_off + p * 16 + bRowL) * ARS + ks * 32 + bColL;
                LDSM_X4(bH[2*p][0], bH[2*p][1], bH[2*p+1][0], bH[2*p+1][1], ad);
                LDSM_X4(bL[2*p][0], bL[2*p][1], bL[2*p+1][0], bL[2*p+1][1], ad + 10240);
            }
            // Pass 1: aH * bH over all 16 independent accumulators
#pragma unroll
            for (int mt = 0; mt < 2; mt++)
#pragma unroll
                for (int nt = 0; nt < 8; nt++)
                    MMA_BF16(acc[mt][nt], aH[mt][0], aH[mt][1], aH[mt][2], aH[mt][3],
                             bH[nt][0], bH[nt][1]);
            // Pass 2: aL * bH
#pragma unroll
            for (int mt = 0; mt < 2; mt++)
#pragma unroll
                for (int nt = 0; nt < 8; nt++)
                    MMA_BF16(acc[mt][nt], aL[mt][0], aL[mt][1], aL[mt][2], aL[mt][3],
                             bH[nt][0], bH[nt][1]);
            // Pass 3: aH * bL
#pragma unroll
            for (int mt = 0; mt < 2; mt++)
#pragma unroll
                for (int nt = 0; nt < 8; nt++)
                    MMA_BF16(acc[mt][nt], aH[mt][0], aH[mt][1], aH[mt][2], aH[mt][3],
                             bL[nt][0], bL[nt][1]);
        }
    }

    // ---- epilogue: bias + relu + (optional) fused BN stats ----
    int gid = lane >> 2, tig = lane & 3;
#pragma unroll
    for (int nt = 0; nt < 8; nt++) {
        int col = bn * 128 + n_off + nt * 8 + tig * 2;
        float b0 = bias[col], b1 = bias[col + 1];
        float s0 = 0.f, s1 = 0.f, q0 = 0.f, q1 = 0.f;
#pragma unroll
        for (int mt = 0; mt < 2; mt++) {
            int r0 = bm * 128 + m_off + mt * 16 + gid;
            float* cc = acc[mt][nt];
            if (r0 < M) {
                float o0 = fmaxf(cc[0] + b0, 0.f);
                float o1 = fmaxf(cc[1] + b1, 0.f);
                float2 o; o.x = o0; o.y = o1;
                *(float2*)(C + (long long)r0 * 256 + col) = o;
                s0 += o0; s1 += o1; q0 += o0 * o0; q1 += o1 * o1;
            }
            if (r0 + 8 < M) {
                float o2 = fmaxf(cc[2] + b0, 0.f);
                float o3 = fmaxf(cc[3] + b1, 0.f);
                float2 o; o.x = o2; o.y = o3;
                *(float2*)(C + (long long)(r0 + 8) * 256 + col) = o;
                s0 += o2; s1 += o3; q0 += o2 * o2; q1 += o3 * o3;
            }
        }
        if (do_stats) {
#pragma unroll
            for (int m = 4; m < 32; m <<= 1) {
                s0 += __shfl_xor_sync(0xffffffffu, s0, m);
                s1 += __shfl_xor_sync(0xffffffffu, s1, m);
                q0 += __shfl_xor_sync(0xffffffffu, q0, m);
                q1 += __shfl_xor_sync(0xffffffffu, q1, m);
            }
            if (gid == 0) {
                atomicAdd(&g_stats[col], s0);
                atomicAdd(&g_stats[col + 1], s1);
                atomicAdd(&g_stats[DIM + col], q0);
                atomicAdd(&g_stats[DIM + col + 1], q1);
            }
        }
    }
}

// ---------------------------------------------------------------------------
// Normalize + layer output + node-feature output slice + pooled sums.
#define ROWS_PB 128
__global__ void bn_apply_kernel(const float* __restrict__ m,
                                const float* __restrict__ g, const float* __restrict__ b,
                                const void* __restrict__ batch,
                                float* __restrict__ hout, float* __restrict__ outn,
                                float* __restrict__ pooled, int layer) {
    int col = threadIdx.x;
    int is64 = g_idx64;
    float mu  = g_stats[col] * (1.f / NN);
    float var = g_stats[DIM + col] * (1.f / NN) - mu * mu;
    float sc  = g[col] * rsqrtf(var + BN_EPS);
    float sh  = b[col] - mu * sc;

    int n0 = blockIdx.x * ROWS_PB;
    int n1 = min(n0 + ROWS_PB, NN);
    float acc = 0.f;
    long long cur = load_idx(batch, n0, is64);
    for (int n = n0; n < n1; n++) {
        float v = m[(long long)n * DIM + col] * sc + sh;
        hout[(long long)n * DIM + col] = v;
        outn[(long long)n * OUTD + layer * DIM + col] = v;
        long long bb = load_idx(batch, n, is64);
        if (bb != cur) {
            atomicAdd(&pooled[cur * OUTD + layer * DIM + col], acc);
            acc = 0.f;
            cur = bb;
        }
        acc += v;
    }
    atomicAdd(&pooled[cur * OUTD + layer * DIM + col], acc);
}

// ---------------------------------------------------------------------------
extern "C" void kernel_launch(void* const* d_in, const int* in_sizes, int n_in,
                              void* d_out, int out_size) {
    const float* x     = (const float*)d_in[0];
    const void*  ei    = d_in[1];
    const void*  batch = d_in[2];

    float* out    = (float*)d_out;
    float* pooled = out;                          // [NG, OUTD]
    float* outn   = out + (long long)NG * OUTD;   // [NN, OUTD]

    float *bufA, *bufB, *bufC, *stats;
    __nv_bfloat16 *whi, *wlo;
    cudaGetSymbolAddress((void**)&bufA, g_bufA4);
    cudaGetSymbolAddress((void**)&bufB, g_bufB4);
    cudaGetSymbolAddress((void**)&bufC, g_bufC4);
    cudaGetSymbolAddress((void**)&stats, g_stats);
    cudaGetSymbolAddress((void**)&whi, g_whi);
    cudaGetSymbolAddress((void**)&wlo, g_wlo);

    const int DSMEM = 2 * STAGE + 256;
    cudaFuncSetAttribute(bf16x3_gemm, cudaFuncAttributeMaxDynamicSharedMemorySize, DSMEM);

    // setup: zeros + dtype detect, edge/weight prep, CSR build
    zeroall_kernel<<<1536, 256>>>(pooled, (const unsigned int*)ei);
    prep_kernel<<<3125, 256>>>(ei,
        (const float*)d_in[3],  (const float*)d_in[5],
        (const float*)d_in[9],  (const float*)d_in[11],
        (const float*)d_in[15], (const float*)d_in[17],
        whi, wlo);
    scan_kernel<<<1, 1024>>>();
    fillcsr_kernel<<<3125, 256>>>();

    const int woffs[6] = {0, 32768, 98304, 163840, 229376, 294912};

    const float* h = x;
    for (int l = 0; l < NL; l++) {
        int F = (l == 0) ? FIN : DIM;
        const float* b1 = (const float*)d_in[3 + 6 * l + 1];
        const float* b2 = (const float*)d_in[3 + 6 * l + 3];
        const float* gg = (const float*)d_in[3 + 6 * l + 4];
        const float* bb = (const float*)d_in[3 + 6 * l + 5];

        // agg = h + sum of in-neighbors (CSR gather, atomic-free)
        gather_kernel<<<6250, 256>>>(h, bufB, F);

        // MLP with 3xBF16 tensor cores; second GEMM fuses BN stats
        dim3 grid((NN + 127) / 128, 2);
        bf16x3_gemm<<<grid, 256, DSMEM>>>(bufB, whi + woffs[2*l],   wlo + woffs[2*l],   b1, bufC, NN, F, 0);
        zero_kernel<<<2, 256>>>(stats, 2 * DIM);
        bf16x3_gemm<<<grid, 256, DSMEM>>>(bufC, whi + woffs[2*l+1], wlo + woffs[2*l+1], b2, bufB, NN, DIM, 1);

        // BatchNorm apply + outputs + pooling
        bn_apply_kernel<<<(NN + ROWS_PB - 1) / ROWS_PB, DIM>>>(
            bufB, gg, bb, batch, bufA, outn, pooled, l);

        h = bufA;
    }
}

// round 10
// speedup vs baseline: 1.0457x; 1.0457x over previous
#include <cuda_runtime.h>
#include <cuda_bf16.h>
#include <stdint.h>

#define NN   50000
#define NE   800000
#define FIN  128
#define DIM  256
#define NG   512
#define NL   3
#define OUTD (NL*DIM)   // 768
#define BN_EPS 1e-5f

// Scratch
__device__ float4 g_bufA4[NN*DIM/4];   // h (layer output)
__device__ float4 g_bufB4[NN*DIM/4];   // agg, then m (post-MLP)
__device__ float4 g_bufC4[NN*DIM/4];   // t (hidden)
__device__ float  g_stats[2*DIM];      // per-column sum, sumsq
__device__ int    g_idx64;             // 1 if edge_index/batch are int64
// Pre-split bf16 weight images, N-major ([n][k]) per (t,chunk) 128x32 tile.
__device__ __nv_bfloat16 g_whi[360448];
__device__ __nv_bfloat16 g_wlo[360448];
// CSR scratch
__device__ int g_deg[NN];
__device__ int g_rowstart[NN];
__device__ int g_pos[NE];
__device__ int g_src32[NE];
__device__ int g_dst32[NE];
__device__ int g_eidx[NE];

// ---------------------------------------------------------------------------
__device__ __forceinline__ uint32_t smem_u32(const void* p) {
    uint32_t a;
    asm("{ .reg .u64 t; cvta.to.shared.u64 t, %1; cvt.u32.u64 %0, t; }" : "=r"(a) : "l"(p));
    return a;
}
__device__ __forceinline__ uint32_t pack_bf2(float a, float b) {
    uint32_t r;
    asm("cvt.rn.bf16x2.f32 %0, %1, %2;" : "=r"(r) : "f"(b), "f"(a));
    return r;
}
__device__ __forceinline__ void splitbf(float x, float& h, float& l) {
    __nv_bfloat16 hb = __float2bfloat16_rn(x);
    h = __bfloat162float(hb);
    l = x - h;
}
#define LDSM_X4(r0, r1, r2, r3, addr)                                          \
    asm volatile("ldmatrix.sync.aligned.m8n8.x4.shared.b16 {%0,%1,%2,%3}, [%4];" \
                 : "=r"(r0), "=r"(r1), "=r"(r2), "=r"(r3) : "r"(addr))
#define MMA_BF16(c, a0, a1, a2, a3, b0, b1)                                    \
    asm volatile(                                                              \
        "mma.sync.aligned.m16n8k16.row.col.f32.bf16.bf16.f32 "                 \
        "{%0,%1,%2,%3}, {%4,%5,%6,%7}, {%8,%9}, {%0,%1,%2,%3};"                \
        : "+f"(c[0]), "+f"(c[1]), "+f"(c[2]), "+f"(c[3])                       \
        : "r"(a0), "r"(a1), "r"(a2), "r"(a3), "r"(b0), "r"(b1))
#define CP_ASYNC16(dst, src)                                                   \
    asm volatile("cp.async.ca.shared.global [%0], [%1], 16;"                   \
                 :: "r"(dst), "l"(src) : "memory")
#define CP_COMMIT() asm volatile("cp.async.commit_group;" ::: "memory")
#define CP_WAIT0()  asm volatile("cp.async.wait_group 0;" ::: "memory")

__device__ __forceinline__ long long load_idx(const void* p, long long i, int is64) {
    return is64 ? ((const long long*)p)[i] : (long long)((const int*)p)[i];
}

// ---------------------------------------------------------------------------
__global__ void zeroall_kernel(float* pooled, const unsigned int* ei_raw) {
    int i = blockIdx.x * blockDim.x + threadIdx.x;
    if (i < NG * OUTD) pooled[i] = 0.f;
    if (i < NN) g_deg[i] = 0;
    if (i == 0) {
        unsigned int z = 0u;
#pragma unroll
        for (int k = 0; k < 32; k++) z |= ei_raw[2*k + 1];
        g_idx64 = (z == 0u) ? 1 : 0;
    }
}

__global__ void zero_kernel(float* p, int n) {
    int i = blockIdx.x * blockDim.x + threadIdx.x;
    if (i < n) p[i] = 0.f;
}

// ---------------------------------------------------------------------------
#define WTOT 360448
__global__ void prep_kernel(const void* __restrict__ ei,
                            const float* w0, const float* w1, const float* w2,
                            const float* w3, const float* w4, const float* w5,
                            __nv_bfloat16* __restrict__ whi,
                            __nv_bfloat16* __restrict__ wlo) {
    int stride = gridDim.x * blockDim.x;
    int gidx = blockIdx.x * blockDim.x + threadIdx.x;
    int is64 = g_idx64;
    for (int e = gidx; e < NE; e += stride) {
        int s = (int)load_idx(ei, e, is64);
        int d = (int)load_idx(ei, (long long)NE + e, is64);
        g_src32[e] = s;
        g_dst32[e] = d;
        g_pos[e] = atomicAdd(&g_deg[d], 1);
    }
    const float* ws[6] = {w0, w1, w2, w3, w4, w5};
    const int woffs[6] = {0, 32768, 98304, 163840, 229376, 294912};
    for (int idx = gidx; idx < WTOT; idx += stride) {
        int wsel, local, K;
        if (idx < 32768) { wsel = 0; local = idx; K = FIN; }
        else { wsel = 1 + ((idx - 32768) >> 16); local = (idx - 32768) & 65535; K = DIM; }
        int k = local >> 8, n = local & 255;
        int nch = K >> 5;
        int t = n >> 7, nl = n & 127, c = k >> 5, kk = k & 31;
        int off = woffs[wsel] + (t * nch + c) * 4096 + nl * 32 + kk;
        float x = ws[wsel][local];
        float h, l;
        splitbf(x, h, l);
        whi[off] = __float2bfloat16_rn(h);
        wlo[off] = __float2bfloat16_rn(l);
    }
}

__global__ void scan_kernel() {
    __shared__ int sm[1024];
    int t = threadIdx.x;
    const int CH = (NN + 1023) / 1024;
    int b0 = t * CH, b1 = min(b0 + CH, NN);
    int s = 0;
    for (int i = b0; i < b1; i++) s += g_deg[i];
    sm[t] = s;
    __syncthreads();
    for (int off = 1; off < 1024; off <<= 1) {
        int v = (t >= off) ? sm[t - off] : 0;
        __syncthreads();
        sm[t] += v;
        __syncthreads();
    }
    int run = (t == 0) ? 0 : sm[t - 1];
    for (int i = b0; i < b1; i++) { g_rowstart[i] = run; run += g_deg[i]; }
}

__global__ void fillcsr_kernel() {
    int stride = gridDim.x * blockDim.x;
    for (int e = blockIdx.x * blockDim.x + threadIdx.x; e < NE; e += stride)
        g_eidx[g_rowstart[g_dst32[e]] + g_pos[e]] = g_src32[e];
}

// ---------------------------------------------------------------------------
// CSR gather: agg[i] = h[i] + sum_{j in in(i)} h[j].  One warp per node.
__global__ void gather_kernel(const float* __restrict__ h, float* __restrict__ agg,
                              int F) {
    int gw = (blockIdx.x * blockDim.x + threadIdx.x) >> 5;
    if (gw >= NN) return;
    int lane = threadIdx.x & 31;
    int start = g_rowstart[gw], deg = g_deg[gw];
    int F4 = F >> 2;
    bool wide = (F4 == 64);
    const float4* hv = (const float4*)h;
    const float4* hp = hv + (long long)gw * F4 + lane;
    float4 a0 = hp[0];
    float4 a1 = wide ? hp[32] : make_float4(0.f, 0.f, 0.f, 0.f);
    for (int i0 = 0; i0 < deg; i0 += 32) {
        int mye = (i0 + lane < deg) ? g_eidx[start + i0 + lane] : 0;
        int cnt = min(32, deg - i0);
        for (int j = 0; j < cnt; j++) {
            int s = __shfl_sync(0xffffffffu, mye, j);
            const float4* sp = hv + (long long)s * F4 + lane;
            float4 v = sp[0];
            a0.x += v.x; a0.y += v.y; a0.z += v.z; a0.w += v.w;
            if (wide) {
                float4 u = sp[32];
                a1.x += u.x; a1.y += u.y; a1.z += u.z; a1.w += u.w;
            }
        }
    }
    float4* op = (float4*)agg + (long long)gw * F4 + lane;
    op[0] = a0;
    if (wide) op[32] = a1;
}

// ---------------------------------------------------------------------------
// 3xBF16 tensor-core GEMM, full-N: C[M,256] = relu(A[M,K] @ W[K,256] + bias).
// 512 threads (16 warps, 4M x 4N), block tile 128x256, BK=32, double-buffered.
// A loaded once per row (fp32->hi/lo split in registers); B via cp.async
// (pre-split bf16 image, no conversion). One wave count: 391 CTAs -> 3 waves.
#define ARS 80
#define AL_OFF 10240
#define BH_OFF 20480
#define BL_OFF 40960
#define STG    61440

__global__ void __launch_bounds__(512) bf16x3_gemm(
    const float* __restrict__ A, const __nv_bfloat16* __restrict__ Whi,
    const __nv_bfloat16* __restrict__ Wlo, const float* __restrict__ bias,
    float* __restrict__ C, int M, int K, int do_stats) {
    extern __shared__ __align__(16) char dsm[];
    int tid = threadIdx.x, wid = tid >> 5, lane = tid & 31;
    int bm = blockIdx.x;
    int nch = K >> 5;

    uint32_t sb = (smem_u32(dsm) + 127) & ~127u;
    int m_off = (wid & 3) * 32;
    int n_off = (wid >> 2) * 64;

    int aRowL = (lane & 7) + ((lane >> 3) & 1) * 8;
    int aColL = (lane >> 4) * 16;
    int bRowL = ((lane >> 4) * 8) + (lane & 7);
    int bColL = ((lane >> 3) & 1) * 16;

    float acc[2][8][4] = {};

    const float* Abase = A + (long long)bm * 128 * K;

    // ---- B cp.async issue for chunk c into stage base stg ----
    // per thread: 2 positions x 2 polarities = 4 cp.async of 16B
    auto issueB = [&](int c, uint32_t stg) {
#pragma unroll
        for (int i = 0; i < 2; i++) {
            int p = tid + i * 512;        // 0..1023 uint4 slots
            int row = p >> 2, seg = p & 3;
            int t = row >> 7, nl = row & 127;
            long long srcIdx = ((long long)(t * nch + c) * 512) + nl * 4 + seg;
            uint32_t dst = stg + BH_OFF + row * ARS + seg * 16;
            CP_ASYNC16(dst, (const uint4*)Whi + srcIdx);
            CP_ASYNC16(dst + (BL_OFF - BH_OFF), (const uint4*)Wlo + srcIdx);
        }
    };

    // ---- prologue: B(0) async, A(0) to registers ----
    issueB(0, sb);
    CP_COMMIT();
    float4 pa[2];
#pragma unroll
    for (int i = 0; i < 2; i++) {
        int pos = tid + i * 512;
        int row = pos >> 3, c4 = pos & 7;
        pa[i] = make_float4(0.f, 0.f, 0.f, 0.f);
        if (bm * 128 + row < M)
            pa[i] = *(const float4*)(Abase + (long long)row * K + c4 * 4);
    }

    for (int c = 0; c < nch; c++) {
        uint32_t stg = sb + (c & 1) * STG;

        // store A(c) hi/lo to smem
#pragma unroll
        for (int i = 0; i < 2; i++) {
            int pos = tid + i * 512;
            int row = pos >> 3, c4 = pos & 7;
            float h0, l0, h1, l1, h2, l2, h3, l3;
            splitbf(pa[i].x, h0, l0); splitbf(pa[i].y, h1, l1);
            splitbf(pa[i].z, h2, l2); splitbf(pa[i].w, h3, l3);
            uint32_t H01 = pack_bf2(h0, h1), H23 = pack_bf2(h2, h3);
            uint32_t L01 = pack_bf2(l0, l1), L23 = pack_bf2(l2, l3);
            uint32_t ad = stg + row * ARS + c4 * 8;
            asm volatile("st.shared.v2.b32 [%0], {%1,%2};"
                         :: "r"(ad), "r"(H01), "r"(H23) : "memory");
            asm volatile("st.shared.v2.b32 [%0], {%1,%2};"
                         :: "r"(ad + AL_OFF), "r"(L01), "r"(L23) : "memory");
        }

        CP_WAIT0();          // B(c) landed
        __syncthreads();     // all stores + cp.async visible; stage s^1 free

        if (c + 1 < nch) {
            issueB(c + 1, sb + ((c + 1) & 1) * STG);
            CP_COMMIT();
            int k0 = (c + 1) * 32;
#pragma unroll
            for (int i = 0; i < 2; i++) {
                int pos = tid + i * 512;
                int row = pos >> 3, c4 = pos & 7;
                pa[i] = make_float4(0.f, 0.f, 0.f, 0.f);
                if (bm * 128 + row < M)
                    pa[i] = *(const float4*)(Abase + (long long)row * K + k0 + c4 * 4);
            }
        }

        // compute stage: 2 k16-steps
#pragma unroll
        for (int ks = 0; ks < 2; ks++) {
            uint32_t aH[2][4], aL[2][4];
#pragma unroll
            for (int mt = 0; mt < 2; mt++) {
                uint32_t ad = stg + (m_off + mt * 16 + aRowL) * ARS + ks * 32 + aColL;
                LDSM_X4(aH[mt][0], aH[mt][1], aH[mt][2], aH[mt][3], ad);
                LDSM_X4(aL[mt][0], aL[mt][1], aL[mt][2], aL[mt][3], ad + AL_OFF);
            }
#pragma unroll
            for (int p = 0; p < 4; p++) {
                uint32_t bH[2][2], bL[2][2];
                uint32_t ad = stg + BH_OFF + (n_off + p * 16 + bRowL) * ARS + ks * 32 + bColL;
                LDSM_X4(bH[0][0], bH[0][1], bH[1][0], bH[1][1], ad);
                LDSM_X4(bL[0][0], bL[0][1], bL[1][0], bL[1][1], ad + (BL_OFF - BH_OFF));
#pragma unroll
                for (int mt = 0; mt < 2; mt++)
#pragma unroll
                    for (int q = 0; q < 2; q++)
                        MMA_BF16(acc[mt][2*p+q], aH[mt][0], aH[mt][1], aH[mt][2], aH[mt][3],
                                 bH[q][0], bH[q][1]);
#pragma unroll
                for (int mt = 0; mt < 2; mt++)
#pragma unroll
                    for (int q = 0; q < 2; q++)
                        MMA_BF16(acc[mt][2*p+q], aL[mt][0], aL[mt][1], aL[mt][2], aL[mt][3],
                                 bH[q][0], bH[q][1]);
#pragma unroll
                for (int mt = 0; mt < 2; mt++)
#pragma unroll
                    for (int q = 0; q < 2; q++)
                        MMA_BF16(acc[mt][2*p+q], aH[mt][0], aH[mt][1], aH[mt][2], aH[mt][3],
                                 bL[q][0], bL[q][1]);
            }
        }
        __syncthreads();
    }

    // ---- epilogue: bias + relu + (optional) fused BN stats ----
    int gid = lane >> 2, tig = lane & 3;
#pragma unroll
    for (int nt = 0; nt < 8; nt++) {
        int col = n_off + nt * 8 + tig * 2;
        float b0 = bias[col], b1 = bias[col + 1];
        float s0 = 0.f, s1 = 0.f, q0 = 0.f, q1 = 0.f;
#pragma unroll
        for (int mt = 0; mt < 2; mt++) {
            int r0 = bm * 128 + m_off + mt * 16 + gid;
            float* cc = acc[mt][nt];
            if (r0 < M) {
                float o0 = fmaxf(cc[0] + b0, 0.f);
                float o1 = fmaxf(cc[1] + b1, 0.f);
                float2 o; o.x = o0; o.y = o1;
                *(float2*)(C + (long long)r0 * 256 + col) = o;
                s0 += o0; s1 += o1; q0 += o0 * o0; q1 += o1 * o1;
            }
            if (r0 + 8 < M) {
                float o2 = fmaxf(cc[2] + b0, 0.f);
                float o3 = fmaxf(cc[3] + b1, 0.f);
                float2 o; o.x = o2; o.y = o3;
                *(float2*)(C + (long long)(r0 + 8) * 256 + col) = o;
                s0 += o2; s1 += o3; q0 += o2 * o2; q1 += o3 * o3;
            }
        }
        if (do_stats) {
#pragma unroll
            for (int m = 4; m < 32; m <<= 1) {
                s0 += __shfl_xor_sync(0xffffffffu, s0, m);
                s1 += __shfl_xor_sync(0xffffffffu, s1, m);
                q0 += __shfl_xor_sync(0xffffffffu, q0, m);
                q1 += __shfl_xor_sync(0xffffffffu, q1, m);
            }
            if (gid == 0) {
                atomicAdd(&g_stats[col], s0);
                atomicAdd(&g_stats[col + 1], s1);
                atomicAdd(&g_stats[DIM + col], q0);
                atomicAdd(&g_stats[DIM + col + 1], q1);
            }
        }
    }
}

// ---------------------------------------------------------------------------
#define ROWS_PB 128
__global__ void bn_apply_kernel(const float* __restrict__ m,
                                const float* __restrict__ g, const float* __restrict__ b,
                                const void* __restrict__ batch,
                                float* __restrict__ hout, float* __restrict__ outn,
                                float* __restrict__ pooled, int layer) {
    int col = threadIdx.x;
    int is64 = g_idx64;
    float mu  = g_stats[col] * (1.f / NN);
    float var = g_stats[DIM + col] * (1.f / NN) - mu * mu;
    float sc  = g[col] * rsqrtf(var + BN_EPS);
    float sh  = b[col] - mu * sc;

    int n0 = blockIdx.x * ROWS_PB;
    int n1 = min(n0 + ROWS_PB, NN);
    float acc = 0.f;
    long long cur = load_idx(batch, n0, is64);
    for (int n = n0; n < n1; n++) {
        float v = m[(long long)n * DIM + col] * sc + sh;
        hout[(long long)n * DIM + col] = v;
        outn[(long long)n * OUTD + layer * DIM + col] = v;
        long long bb = load_idx(batch, n, is64);
        if (bb != cur) {
            atomicAdd(&pooled[cur * OUTD + layer * DIM + col], acc);
            acc = 0.f;
            cur = bb;
        }
        acc += v;
    }
    atomicAdd(&pooled[cur * OUTD + layer * DIM + col], acc);
}

// ---------------------------------------------------------------------------
extern "C" void kernel_launch(void* const* d_in, const int* in_sizes, int n_in,
                              void* d_out, int out_size) {
    const float* x     = (const float*)d_in[0];
    const void*  ei    = d_in[1];
    const void*  batch = d_in[2];

    float* out    = (float*)d_out;
    float* pooled = out;                          // [NG, OUTD]
    float* outn   = out + (long long)NG * OUTD;   // [NN, OUTD]

    float *bufA, *bufB, *bufC, *stats;
    __nv_bfloat16 *whi, *wlo;
    cudaGetSymbolAddress((void**)&bufA, g_bufA4);
    cudaGetSymbolAddress((void**)&bufB, g_bufB4);
    cudaGetSymbolAddress((void**)&bufC, g_bufC4);
    cudaGetSymbolAddress((void**)&stats, g_stats);
    cudaGetSymbolAddress((void**)&whi, g_whi);
    cudaGetSymbolAddress((void**)&wlo, g_wlo);

    const int DSMEM = 2 * STG + 256;   // 123136
    cudaFuncSetAttribute(bf16x3_gemm, cudaFuncAttributeMaxDynamicSharedMemorySize, DSMEM);

    // setup: zeros + dtype detect, edge/weight prep, CSR build
    zeroall_kernel<<<1536, 256>>>(pooled, (const unsigned int*)ei);
    prep_kernel<<<3125, 256>>>(ei,
        (const float*)d_in[3],  (const float*)d_in[5],
        (const float*)d_in[9],  (const float*)d_in[11],
        (const float*)d_in[15], (const float*)d_in[17],
        whi, wlo);
    scan_kernel<<<1, 1024>>>();
    fillcsr_kernel<<<3125, 256>>>();

    const int woffs[6] = {0, 32768, 98304, 163840, 229376, 294912};

    const float* h = x;
    for (int l = 0; l < NL; l++) {
        int F = (l == 0) ? FIN : DIM;
        const float* b1 = (const float*)d_in[3 + 6 * l + 1];
        const float* b2 = (const float*)d_in[3 + 6 * l + 3];
        const float* gg = (const float*)d_in[3 + 6 * l + 4];
        const float* bb = (const float*)d_in[3 + 6 * l + 5];

        // agg = h + sum of in-neighbors (CSR gather, atomic-free)
        gather_kernel<<<6250, 256>>>(h, bufB, F);

        // MLP with 3xBF16 tensor cores (full N per CTA); GEMM2 fuses BN stats
        int grid = (NN + 127) / 128;
        bf16x3_gemm<<<grid, 512, DSMEM>>>(bufB, whi + woffs[2*l],   wlo + woffs[2*l],   b1, bufC, NN, F, 0);
        zero_kernel<<<2, 256>>>(stats, 2 * DIM);
        bf16x3_gemm<<<grid, 512, DSMEM>>>(bufC, whi + woffs[2*l+1], wlo + woffs[2*l+1], b2, bufB, NN, DIM, 1);

        // BatchNorm apply + outputs + pooling
        bn_apply_kernel<<<(NN + ROWS_PB - 1) / ROWS_PB, DIM>>>(
            bufB, gg, bb, batch, bufA, outn, pooled, l);

        h = bufA;
    }
}